// round 4
// baseline (speedup 1.0000x reference)
#include <cuda_runtime.h>

#define FULL 0xffffffffu
constexpr int NW = 10;   // wires
constexpr int NL = 4;    // layers

// Layer-1 fused gate bases: G = RY(th) * RZ(phi) (om pushed into phase tables)
__device__ float4 g_rot[NW * 2];
// Layers 2-4 RY coefficients: (cos(th/2), sin(th/2))
__device__ float2 g_rycs[3 * NW];
// Phase tables Gamma_g (g=0..2), packed per amplitude pair:
//  g_phA = (cr0, cr1, -ci0, -ci1),  g_phB = (ci0, ci1)
__device__ float4 g_phA[3 * 512];
__device__ float2 g_phB[3 * 512];

// ---------------------------------------------------------------------------
// Prep: gate matrices + composed diagonal phase tables. One block, 1024 thr.
// ---------------------------------------------------------------------------
__global__ void prep_kernel(const float* __restrict__ w) {
    __shared__ float s_ang[1024], s_co[1024], s_si[1024];
    int v = threadIdx.x;

    if (v < NL * NW) {
        int l = v / NW, wi = v % NW;
        float phi = w[v * 3 + 0], th = w[v * 3 + 1];
        float s, c;
        sincosf(0.5f * th, &s, &c);
        if (l == 0) {
            float sp, cp;  // e^{-i phi/2} = cp + i sp
            sincosf(-0.5f * phi, &sp, &cp);
            // G = RY(th) RZ(phi):
            // G00 = c e^{-iphi/2}; G01 = -s e^{+iphi/2}; G10 = s e^{-iphi/2}; G11 = c e^{+iphi/2}
            g_rot[wi * 2 + 0] = make_float4(c * cp, c * sp, -s * cp, s * sp);
            g_rot[wi * 2 + 1] = make_float4(s * cp, s * sp, c * cp, -c * sp);
        } else {
            g_rycs[(l - 1) * NW + wi] = make_float2(c, s);
        }
    }

    for (int g = 0; g < 3; ++g) {
        __syncthreads();
        // delta1 (RZ(om) of layer g) pushed through ring r=g+1:
        // tmp[pi(u)] = a1(u)  =>  tmp[v] = a1(pi^{-1}(v))
        float a1 = 0.0f;
#pragma unroll
        for (int wi = 0; wi < NW; ++wi) {
            float om = w[(g * NW + wi) * 3 + 2];
            a1 += (((v >> (9 - wi)) & 1) ? 0.5f : -0.5f) * om;
        }
        int u = v, r = g + 1;
#pragma unroll
        for (int wi = 0; wi < NW; ++wi) {
            int pc = 9 - wi, pt = 9 - ((wi + r) % NW);
            if ((u >> pc) & 1) u ^= (1 << pt);
        }
        s_ang[u] = a1;
        __syncthreads();
        // add delta2 (RZ(phi) of layer g+1)
        float a = s_ang[v];
#pragma unroll
        for (int wi = 0; wi < NW; ++wi) {
            float phi = w[((g + 1) * NW + wi) * 3 + 0];
            a += (((v >> (9 - wi)) & 1) ? 0.5f : -0.5f) * phi;
        }
        float si, co;
        sincosf(a, &si, &co);
        s_co[v] = co;
        s_si[v] = si;
        __syncthreads();
        if (v < 512) {
            int v0 = 2 * v, v1 = 2 * v + 1;
            g_phA[g * 512 + v] = make_float4(s_co[v0], s_co[v1], -s_si[v0], -s_si[v1]);
            g_phB[g * 512 + v] = make_float2(s_si[v0], s_si[v1]);
        }
    }
}

// ---------------------------------------------------------------------------
// Packed f32x2 helpers
// ---------------------------------------------------------------------------
__device__ __forceinline__ float2 f2fma(float2 a, float2 b, float2 c) {
    float2 d;
    asm("{\n\t"
        ".reg .b64 ra, rb, rc, rd;\n\t"
        "mov.b64 ra, {%2, %3};\n\t"
        "mov.b64 rb, {%4, %5};\n\t"
        "mov.b64 rc, {%6, %7};\n\t"
        "fma.rn.f32x2 rd, ra, rb, rc;\n\t"
        "mov.b64 {%0, %1}, rd;\n\t"
        "}"
        : "=f"(d.x), "=f"(d.y)
        : "f"(a.x), "f"(a.y), "f"(b.x), "f"(b.y), "f"(c.x), "f"(c.y));
    return d;
}
__device__ __forceinline__ float2 f2mul(float2 a, float2 b) {
    float2 d;
    asm("{\n\t"
        ".reg .b64 ra, rb, rd;\n\t"
        "mov.b64 ra, {%2, %3};\n\t"
        "mov.b64 rb, {%4, %5};\n\t"
        "mul.rn.f32x2 rd, ra, rb;\n\t"
        "mov.b64 {%0, %1}, rd;\n\t"
        "}"
        : "=f"(d.x), "=f"(d.y)
        : "f"(a.x), "f"(a.y), "f"(b.x), "f"(b.y));
    return d;
}
__device__ __forceinline__ float2 pk(float v) { return make_float2(v, v); }
__device__ __forceinline__ float2 swp(float2 v) { return make_float2(v.y, v.x); }

__device__ __forceinline__ float2 shx2(float2 v, int mask) {
    float2 r;
    r.x = __shfl_xor_sync(FULL, v.x, mask);
    r.y = __shfl_xor_sync(FULL, v.y, mask);
    return r;
}
__device__ __forceinline__ float2 shidx2(float2 v, int src) {
    float2 r;
    r.x = __shfl_sync(FULL, v.x, src);
    r.y = __shfl_sync(FULL, v.y, src);
    return r;
}

// ---------------------------------------------------------------------------
// Layout: amplitude index bit for wire W is p = 9 - W.
//   bits 9..5 -> lane bits, bits 4..1 -> register index, bit 0 -> packed half
// ---------------------------------------------------------------------------

// General complex 2x2 on wire W (layer 1 only)
template <int W>
__device__ __forceinline__ void applyMat(float2 RE[16], float2 IM[16], int lane,
                                         float2 U00, float2 U01, float2 U10, float2 U11) {
    constexpr int p = 9 - W;
    if constexpr (p >= 5) {
        constexpr int lb = p - 5;
        int bit = (lane >> lb) & 1;
        float2 co = bit ? U11 : U00;
        float2 ct = bit ? U10 : U01;
        const float2 cox = pk(co.x), coy = pk(co.y), ncoy = pk(-co.y);
        const float2 ctx = pk(ct.x), cty = pk(ct.y), ncty = pk(-ct.y);
#pragma unroll
        for (int k = 0; k < 16; ++k) {
            float2 ore = shx2(RE[k], 1 << lb);
            float2 oim = shx2(IM[k], 1 << lb);
            float2 nre = f2fma(ncty, oim, f2fma(ctx, ore, f2fma(ncoy, IM[k], f2mul(cox, RE[k]))));
            float2 nim = f2fma(cty, ore, f2fma(ctx, oim, f2fma(coy, RE[k], f2mul(cox, IM[k]))));
            RE[k] = nre; IM[k] = nim;
        }
    } else if constexpr (p >= 1) {
        constexpr int kb = 1 << (p - 1);
        const float2 u00x = pk(U00.x), u00y = pk(U00.y), nu00y = pk(-U00.y);
        const float2 u01x = pk(U01.x), u01y = pk(U01.y), nu01y = pk(-U01.y);
        const float2 u10x = pk(U10.x), u10y = pk(U10.y), nu10y = pk(-U10.y);
        const float2 u11x = pk(U11.x), u11y = pk(U11.y), nu11y = pk(-U11.y);
#pragma unroll
        for (int k = 0; k < 16; ++k) {
            if (!(k & kb)) {
                const int j = k | kb;
                float2 a0re = RE[k], a0im = IM[k], a1re = RE[j], a1im = IM[j];
                RE[k] = f2fma(nu01y, a1im, f2fma(u01x, a1re, f2fma(nu00y, a0im, f2mul(u00x, a0re))));
                IM[k] = f2fma(u01y, a1re, f2fma(u01x, a1im, f2fma(u00y, a0re, f2mul(u00x, a0im))));
                RE[j] = f2fma(nu11y, a1im, f2fma(u11x, a1re, f2fma(nu10y, a0im, f2mul(u10x, a0re))));
                IM[j] = f2fma(u11y, a1re, f2fma(u11x, a1im, f2fma(u10y, a0re, f2mul(u10x, a0im))));
            }
        }
    } else {
        const float2 c00x = make_float2(U00.x, U10.x), c00y = make_float2(U00.y, U10.y);
        const float2 c01x = make_float2(U01.x, U11.x), c01y = make_float2(U01.y, U11.y);
        const float2 n00y = make_float2(-U00.y, -U10.y), n01y = make_float2(-U01.y, -U11.y);
#pragma unroll
        for (int k = 0; k < 16; ++k) {
            float a0r = RE[k].x, a0i = IM[k].x, a1r = RE[k].y, a1i = IM[k].y;
            float2 nre = f2fma(n01y, pk(a1i), f2fma(c01x, pk(a1r),
                          f2fma(n00y, pk(a0i), f2mul(c00x, pk(a0r)))));
            float2 nim = f2fma(c01y, pk(a1r), f2fma(c01x, pk(a1i),
                          f2fma(c00y, pk(a0r), f2mul(c00x, pk(a0i)))));
            RE[k] = nre; IM[k] = nim;
        }
    }
}

// Real RY on wire W: 4 f2-ops per register
template <int W>
__device__ __forceinline__ void ryGate(float2 RE[16], float2 IM[16], int lane, float c, float s) {
    constexpr int p = 9 - W;
    if constexpr (p >= 5) {
        constexpr int lb = p - 5;
        int bit = (lane >> lb) & 1;
        float sg = bit ? s : -s;
        const float2 cp = pk(c), sp = pk(sg);
#pragma unroll
        for (int k = 0; k < 16; ++k) {
            float2 ore = shx2(RE[k], 1 << lb);
            float2 oim = shx2(IM[k], 1 << lb);
            RE[k] = f2fma(cp, RE[k], f2mul(sp, ore));
            IM[k] = f2fma(cp, IM[k], f2mul(sp, oim));
        }
    } else if constexpr (p >= 1) {
        constexpr int kb = 1 << (p - 1);
        const float2 cp = pk(c), sp = pk(s), np = pk(-s);
#pragma unroll
        for (int k = 0; k < 16; ++k) {
            if (!(k & kb)) {
                const int j = k | kb;
                float2 a0re = RE[k], a0im = IM[k], a1re = RE[j], a1im = IM[j];
                RE[k] = f2fma(cp, a0re, f2mul(np, a1re));
                IM[k] = f2fma(cp, a0im, f2mul(np, a1im));
                RE[j] = f2fma(cp, a1re, f2mul(sp, a0re));
                IM[j] = f2fma(cp, a1im, f2mul(sp, a0im));
            }
        }
    } else {
        // p == 0: free half-swap butterfly
        const float2 cp = pk(c), ss = make_float2(-s, s);
#pragma unroll
        for (int k = 0; k < 16; ++k) {
            RE[k] = f2fma(cp, RE[k], f2mul(ss, swp(RE[k])));
            IM[k] = f2fma(cp, IM[k], f2mul(ss, swp(IM[k])));
        }
    }
}

// Gamma (composed diagonal): per-register phase multiply
__device__ __forceinline__ void applyPhase(float2 RE[16], float2 IM[16], int lane, int g) {
    const float4* A = g_phA + g * 512 + (lane << 4);
    const float2* Bv = g_phB + g * 512 + (lane << 4);
#pragma unroll
    for (int k = 0; k < 16; ++k) {
        float4 a = A[k];
        float2 ci = Bv[k];
        float2 cr = make_float2(a.x, a.y), nci = make_float2(a.z, a.w);
        float2 nre = f2fma(cr, RE[k], f2mul(nci, IM[k]));
        float2 nim = f2fma(cr, IM[k], f2mul(ci, RE[k]));
        RE[k] = nre; IM[k] = nim;
    }
}

// ---------------------------------------------------------------------------
// CNOT cases
// ---------------------------------------------------------------------------
template <int CW, int TW>
__device__ __forceinline__ void cnotGate(float2 RE[16], float2 IM[16], int lane) {
    constexpr int pc = 9 - CW, pt = 9 - TW;
    if constexpr (pc >= 1 && pc <= 4 && pt >= 1 && pt <= 4) {
        constexpr int cm = 1 << (pc - 1), tm = 1 << (pt - 1);
#pragma unroll
        for (int k = 0; k < 16; ++k) {
            if ((k & cm) && !(k & tm)) {
                float2 a = RE[k]; RE[k] = RE[k | tm]; RE[k | tm] = a;
                float2 b = IM[k]; IM[k] = IM[k | tm]; IM[k | tm] = b;
            }
        }
    } else if constexpr (pc >= 1 && pc <= 4 && pt >= 5) {
        constexpr int cm = 1 << (pc - 1), tlm = 1 << (pt - 5);
#pragma unroll
        for (int k = 0; k < 16; ++k) {
            if (k & cm) { RE[k] = shx2(RE[k], tlm); IM[k] = shx2(IM[k], tlm); }
        }
    } else if constexpr (pc >= 1 && pc <= 4 && pt == 0) {
        constexpr int cm = 1 << (pc - 1);
#pragma unroll
        for (int k = 0; k < 16; ++k) {
            if (k & cm) { RE[k] = swp(RE[k]); IM[k] = swp(IM[k]); }
        }
    } else if constexpr (pc >= 5 && pt >= 1 && pt <= 4) {
        constexpr int tm = 1 << (pt - 1);
        bool c1 = (lane >> (pc - 5)) & 1;
#pragma unroll
        for (int k = 0; k < 16; ++k) {
            if (!(k & tm)) {
                float2 a = RE[k], b = RE[k | tm];
                RE[k] = c1 ? b : a; RE[k | tm] = c1 ? a : b;
                float2 e = IM[k], f = IM[k | tm];
                IM[k] = c1 ? f : e; IM[k | tm] = c1 ? e : f;
            }
        }
    } else if constexpr (pc >= 5 && pt == 0) {
        bool c1 = (lane >> (pc - 5)) & 1;
#pragma unroll
        for (int k = 0; k < 16; ++k) {
            float2 a = RE[k], b = IM[k];
            RE[k] = c1 ? swp(a) : a;
            IM[k] = c1 ? swp(b) : b;
        }
    } else if constexpr (pc == 0 && pt >= 5) {
        constexpr int tlm = 1 << (pt - 5);
#pragma unroll
        for (int k = 0; k < 16; ++k) {
            RE[k].y = __shfl_xor_sync(FULL, RE[k].y, tlm);
            IM[k].y = __shfl_xor_sync(FULL, IM[k].y, tlm);
        }
    } else if constexpr (pc == 0 && pt >= 1 && pt <= 4) {
        constexpr int tm = 1 << (pt - 1);
#pragma unroll
        for (int k = 0; k < 16; ++k) {
            if (!(k & tm)) {
                float t = RE[k].y; RE[k].y = RE[k | tm].y; RE[k | tm].y = t;
                float u = IM[k].y; IM[k].y = IM[k | tm].y; IM[k | tm].y = u;
            }
        }
    } else {
        constexpr int tlm = 1 << (pt - 5);
        int src = ((lane >> (pc - 5)) & 1) ? (lane ^ tlm) : lane;
#pragma unroll
        for (int k = 0; k < 16; ++k) { RE[k] = shidx2(RE[k], src); IM[k] = shidx2(IM[k], src); }
    }
}

// ---------------------------------------------------------------------------
// Sequencers
// ---------------------------------------------------------------------------
// Fused layer-1: F = [RY(th)RZ(phi)] * RY(x*pi/2)
template <int W>
__device__ __forceinline__ void fusedSeq(float2 RE[16], float2 IM[16], int lane,
                                         float myc, float mys) {
    float cw = __shfl_sync(FULL, myc, W);
    float sw = __shfl_sync(FULL, mys, W);
    float4 g0 = g_rot[W * 2 + 0];
    float4 g1 = g_rot[W * 2 + 1];
    float2 U00 = make_float2(g0.x, g0.y), U01 = make_float2(g0.z, g0.w);
    float2 U10 = make_float2(g1.x, g1.y), U11 = make_float2(g1.z, g1.w);
    float2 F00 = make_float2(fmaf(U00.x, cw, U01.x * sw), fmaf(U00.y, cw, U01.y * sw));
    float2 F01 = make_float2(fmaf(U01.x, cw, -U00.x * sw), fmaf(U01.y, cw, -U00.y * sw));
    float2 F10 = make_float2(fmaf(U10.x, cw, U11.x * sw), fmaf(U10.y, cw, U11.y * sw));
    float2 F11 = make_float2(fmaf(U11.x, cw, -U10.x * sw), fmaf(U11.y, cw, -U10.y * sw));
    applyMat<W>(RE, IM, lane, F00, F01, F10, F11);
    if constexpr (W < NW - 1) fusedSeq<W + 1>(RE, IM, lane, myc, mys);
}

// RY layer (layers 2-4), coefficients from g_rycs row
template <int W>
__device__ __forceinline__ void rySeq(float2 RE[16], float2 IM[16], int lane,
                                      const float2* __restrict__ cs) {
    float2 p = cs[W];
    ryGate<W>(RE, IM, lane, p.x, p.y);
    if constexpr (W < NW - 1) rySeq<W + 1>(RE, IM, lane, cs);
}

template <int R, int W>
__device__ __forceinline__ void cnotRest(float2 RE[16], float2 IM[16], int lane) {
    cnotGate<W, (W + R) % NW>(RE, IM, lane);
    if constexpr (W < NW - 1) cnotRest<R, W + 1>(RE, IM, lane);
}

template <int R>
__device__ __forceinline__ void cnotLayer(float2 RE[16], float2 IM[16], int lane) {
    int src = lane;
#pragma unroll
    for (int w = 4 - R; w >= 0; --w) {
        int cb = 4 - w, tb = 4 - w - R;
        src ^= (((src >> cb) & 1) << tb);
    }
#pragma unroll
    for (int k = 0; k < 16; ++k) { RE[k] = shidx2(RE[k], src); IM[k] = shidx2(IM[k], src); }
    cnotRest<R, 5 - R>(RE, IM, lane);
}

// ---------------------------------------------------------------------------
// Main kernel
// ---------------------------------------------------------------------------
__global__ void __launch_bounds__(128, 4)
vqc_kernel(const float* __restrict__ X, const float* __restrict__ bias,
           float* __restrict__ out, int B) {
    int warp = (blockIdx.x * blockDim.x + threadIdx.x) >> 5;
    int lane = threadIdx.x & 31;
    if (warp >= B) return;

    float x = (lane < NW) ? X[warp * NW + lane] : 0.0f;
    float mys, myc;
    sincosf(x * 0.78539816339744831f, &mys, &myc);

    float2 RE[16], IM[16];
#pragma unroll
    for (int k = 0; k < 16; ++k) { RE[k] = make_float2(0.f, 0.f); IM[k] = make_float2(0.f, 0.f); }
    RE[0].x = (lane == 0) ? 1.0f : 0.0f;

    // Layer 1 (encoding fused, RZ(om) deferred) + ring 1
    fusedSeq<0>(RE, IM, lane, myc, mys);
    cnotLayer<1>(RE, IM, lane);

    // Layers 2-4: Gamma (composed diagonals) + real RY layer + ring
#pragma unroll 1
    for (int g = 0; g < 3; ++g) {
        applyPhase(RE, IM, lane, g);
        rySeq<0>(RE, IM, lane, g_rycs + g * NW);
        switch (g) {
            case 0: cnotLayer<2>(RE, IM, lane); break;
            case 1: cnotLayer<3>(RE, IM, lane); break;
            default: break;  // ring 4 deferred to measurement mask
        }
    }

    // Z on wire 9 through deferred ring 4: parity mask half ^ k_bit3 ^ lane_bit3
    float2 accA = make_float2(0.f, 0.f);
    float2 accB = make_float2(0.f, 0.f);
#pragma unroll
    for (int k = 0; k < 8; ++k)
        accA = f2fma(RE[k], RE[k], f2fma(IM[k], IM[k], accA));
#pragma unroll
    for (int k = 8; k < 16; ++k)
        accB = f2fma(RE[k], RE[k], f2fma(IM[k], IM[k], accB));
    float z = (accA.x - accA.y) - (accB.x - accB.y);
    if ((lane >> 3) & 1) z = -z;
#pragma unroll
    for (int o = 16; o; o >>= 1) z += __shfl_xor_sync(FULL, z, o);
    if (lane == 0) out[warp] = z + bias[0];
}

// ---------------------------------------------------------------------------
extern "C" void kernel_launch(void* const* d_in, const int* in_sizes, int n_in,
                              void* d_out, int out_size) {
    const float* X = (const float*)d_in[0];
    const float* w = (const float*)d_in[1];
    const float* bias = (const float*)d_in[2];
    float* out = (float*)d_out;

    int B = in_sizes[0] / NW;

    prep_kernel<<<1, 1024>>>(w);

    int blocks = (B + 3) / 4;  // 4 warps per 128-thread block
    vqc_kernel<<<blocks, 128>>>(X, bias, out, B);
}

// round 5
// speedup vs baseline: 2.0810x; 2.0810x over previous
#include <cuda_runtime.h>

#define FULL 0xffffffffu
constexpr int NW = 10;   // wires
constexpr int NL = 4;    // layers

// Layer-1 fused gate bases: G = RY(th) * RZ(phi) (om pushed into phase tables)
__device__ float4 g_rot[NW * 2];
// Layers 2-4 RY coefficients: (cos(th/2), sin(th/2))
__device__ float2 g_rycs[3 * NW];
// Phase tables Gamma_g (g=0..2), pair p=(amp>>1) stored TRANSPOSED at
// idx = ((p&15)<<5) | (p>>4)  i.e. [k][lane] order for coalesced warp loads.
//  g_phA = (cr0, cr1, -ci0, -ci1),  g_phB = (ci0, ci1)
__device__ float4 g_phA[3 * 512];
__device__ float2 g_phB[3 * 512];

// ---------------------------------------------------------------------------
// Prep: gate matrices + composed diagonal phase tables. One block, 1024 thr.
// ---------------------------------------------------------------------------
__global__ void prep_kernel(const float* __restrict__ w) {
    __shared__ float s_ang[1024], s_co[1024], s_si[1024];
    int v = threadIdx.x;

    if (v < NL * NW) {
        int l = v / NW, wi = v % NW;
        float phi = w[v * 3 + 0], th = w[v * 3 + 1];
        float s, c;
        sincosf(0.5f * th, &s, &c);
        if (l == 0) {
            float sp, cp;  // e^{-i phi/2} = cp + i sp
            sincosf(-0.5f * phi, &sp, &cp);
            // G = RY(th) RZ(phi)
            g_rot[wi * 2 + 0] = make_float4(c * cp, c * sp, -s * cp, s * sp);
            g_rot[wi * 2 + 1] = make_float4(s * cp, s * sp, c * cp, -c * sp);
        } else {
            g_rycs[(l - 1) * NW + wi] = make_float2(c, s);
        }
    }

    for (int g = 0; g < 3; ++g) {
        __syncthreads();
        // delta1 (RZ(om) of layer g) pushed through ring r=g+1:
        // tmp[pi(u)] = a1(u)
        float a1 = 0.0f;
#pragma unroll
        for (int wi = 0; wi < NW; ++wi) {
            float om = w[(g * NW + wi) * 3 + 2];
            a1 += (((v >> (9 - wi)) & 1) ? 0.5f : -0.5f) * om;
        }
        int u = v, r = g + 1;
#pragma unroll
        for (int wi = 0; wi < NW; ++wi) {
            int pc = 9 - wi, pt = 9 - ((wi + r) % NW);
            if ((u >> pc) & 1) u ^= (1 << pt);
        }
        s_ang[u] = a1;
        __syncthreads();
        // add delta2 (RZ(phi) of layer g+1)
        float a = s_ang[v];
#pragma unroll
        for (int wi = 0; wi < NW; ++wi) {
            float phi = w[((g + 1) * NW + wi) * 3 + 0];
            a += (((v >> (9 - wi)) & 1) ? 0.5f : -0.5f) * phi;
        }
        float si, co;
        sincosf(a, &si, &co);
        s_co[v] = co;
        s_si[v] = si;
        __syncthreads();
        if (v < 512) {
            int v0 = 2 * v, v1 = 2 * v + 1;
            // transposed index: [k][lane] with k = v&15, lane = v>>4
            int idx = ((v & 15) << 5) | (v >> 4);
            g_phA[g * 512 + idx] = make_float4(s_co[v0], s_co[v1], -s_si[v0], -s_si[v1]);
            g_phB[g * 512 + idx] = make_float2(s_si[v0], s_si[v1]);
        }
    }
}

// ---------------------------------------------------------------------------
// Packed f32x2 helpers
// ---------------------------------------------------------------------------
__device__ __forceinline__ float2 f2fma(float2 a, float2 b, float2 c) {
    float2 d;
    asm("{\n\t"
        ".reg .b64 ra, rb, rc, rd;\n\t"
        "mov.b64 ra, {%2, %3};\n\t"
        "mov.b64 rb, {%4, %5};\n\t"
        "mov.b64 rc, {%6, %7};\n\t"
        "fma.rn.f32x2 rd, ra, rb, rc;\n\t"
        "mov.b64 {%0, %1}, rd;\n\t"
        "}"
        : "=f"(d.x), "=f"(d.y)
        : "f"(a.x), "f"(a.y), "f"(b.x), "f"(b.y), "f"(c.x), "f"(c.y));
    return d;
}
__device__ __forceinline__ float2 f2mul(float2 a, float2 b) {
    float2 d;
    asm("{\n\t"
        ".reg .b64 ra, rb, rd;\n\t"
        "mov.b64 ra, {%2, %3};\n\t"
        "mov.b64 rb, {%4, %5};\n\t"
        "mul.rn.f32x2 rd, ra, rb;\n\t"
        "mov.b64 {%0, %1}, rd;\n\t"
        "}"
        : "=f"(d.x), "=f"(d.y)
        : "f"(a.x), "f"(a.y), "f"(b.x), "f"(b.y));
    return d;
}
__device__ __forceinline__ float2 pk(float v) { return make_float2(v, v); }
__device__ __forceinline__ float2 swp(float2 v) { return make_float2(v.y, v.x); }

__device__ __forceinline__ float2 shx2(float2 v, int mask) {
    float2 r;
    r.x = __shfl_xor_sync(FULL, v.x, mask);
    r.y = __shfl_xor_sync(FULL, v.y, mask);
    return r;
}
__device__ __forceinline__ float2 shidx2(float2 v, int src) {
    float2 r;
    r.x = __shfl_sync(FULL, v.x, src);
    r.y = __shfl_sync(FULL, v.y, src);
    return r;
}

// ---------------------------------------------------------------------------
// Layout: amplitude index bit for wire W is p = 9 - W.
//   bits 9..5 -> lane bits, bits 4..1 -> register index, bit 0 -> packed half
// ---------------------------------------------------------------------------

// General complex 2x2 on wire W (layer 1 only)
template <int W>
__device__ __forceinline__ void applyMat(float2 RE[16], float2 IM[16], int lane,
                                         float2 U00, float2 U01, float2 U10, float2 U11) {
    constexpr int p = 9 - W;
    if constexpr (p >= 5) {
        constexpr int lb = p - 5;
        int bit = (lane >> lb) & 1;
        float2 co = bit ? U11 : U00;
        float2 ct = bit ? U10 : U01;
        const float2 cox = pk(co.x), coy = pk(co.y), ncoy = pk(-co.y);
        const float2 ctx = pk(ct.x), cty = pk(ct.y), ncty = pk(-ct.y);
#pragma unroll
        for (int k = 0; k < 16; ++k) {
            float2 ore = shx2(RE[k], 1 << lb);
            float2 oim = shx2(IM[k], 1 << lb);
            float2 nre = f2fma(ncty, oim, f2fma(ctx, ore, f2fma(ncoy, IM[k], f2mul(cox, RE[k]))));
            float2 nim = f2fma(cty, ore, f2fma(ctx, oim, f2fma(coy, RE[k], f2mul(cox, IM[k]))));
            RE[k] = nre; IM[k] = nim;
        }
    } else if constexpr (p >= 1) {
        constexpr int kb = 1 << (p - 1);
        const float2 u00x = pk(U00.x), u00y = pk(U00.y), nu00y = pk(-U00.y);
        const float2 u01x = pk(U01.x), u01y = pk(U01.y), nu01y = pk(-U01.y);
        const float2 u10x = pk(U10.x), u10y = pk(U10.y), nu10y = pk(-U10.y);
        const float2 u11x = pk(U11.x), u11y = pk(U11.y), nu11y = pk(-U11.y);
#pragma unroll
        for (int k = 0; k < 16; ++k) {
            if (!(k & kb)) {
                const int j = k | kb;
                float2 a0re = RE[k], a0im = IM[k], a1re = RE[j], a1im = IM[j];
                RE[k] = f2fma(nu01y, a1im, f2fma(u01x, a1re, f2fma(nu00y, a0im, f2mul(u00x, a0re))));
                IM[k] = f2fma(u01y, a1re, f2fma(u01x, a1im, f2fma(u00y, a0re, f2mul(u00x, a0im))));
                RE[j] = f2fma(nu11y, a1im, f2fma(u11x, a1re, f2fma(nu10y, a0im, f2mul(u10x, a0re))));
                IM[j] = f2fma(u11y, a1re, f2fma(u11x, a1im, f2fma(u10y, a0re, f2mul(u10x, a0im))));
            }
        }
    } else {
        const float2 c00x = make_float2(U00.x, U10.x), c00y = make_float2(U00.y, U10.y);
        const float2 c01x = make_float2(U01.x, U11.x), c01y = make_float2(U01.y, U11.y);
        const float2 n00y = make_float2(-U00.y, -U10.y), n01y = make_float2(-U01.y, -U11.y);
#pragma unroll
        for (int k = 0; k < 16; ++k) {
            float a0r = RE[k].x, a0i = IM[k].x, a1r = RE[k].y, a1i = IM[k].y;
            float2 nre = f2fma(n01y, pk(a1i), f2fma(c01x, pk(a1r),
                          f2fma(n00y, pk(a0i), f2mul(c00x, pk(a0r)))));
            float2 nim = f2fma(c01y, pk(a1r), f2fma(c01x, pk(a1i),
                          f2fma(c00y, pk(a0r), f2mul(c00x, pk(a0i)))));
            RE[k] = nre; IM[k] = nim;
        }
    }
}

// Real RY on wire W: 4 f2-ops per register
template <int W>
__device__ __forceinline__ void ryGate(float2 RE[16], float2 IM[16], int lane, float c, float s) {
    constexpr int p = 9 - W;
    if constexpr (p >= 5) {
        constexpr int lb = p - 5;
        int bit = (lane >> lb) & 1;
        float sg = bit ? s : -s;
        const float2 cp = pk(c), sp = pk(sg);
#pragma unroll
        for (int k = 0; k < 16; ++k) {
            float2 ore = shx2(RE[k], 1 << lb);
            float2 oim = shx2(IM[k], 1 << lb);
            RE[k] = f2fma(cp, RE[k], f2mul(sp, ore));
            IM[k] = f2fma(cp, IM[k], f2mul(sp, oim));
        }
    } else if constexpr (p >= 1) {
        constexpr int kb = 1 << (p - 1);
        const float2 cp = pk(c), sp = pk(s), np = pk(-s);
#pragma unroll
        for (int k = 0; k < 16; ++k) {
            if (!(k & kb)) {
                const int j = k | kb;
                float2 a0re = RE[k], a0im = IM[k], a1re = RE[j], a1im = IM[j];
                RE[k] = f2fma(cp, a0re, f2mul(np, a1re));
                IM[k] = f2fma(cp, a0im, f2mul(np, a1im));
                RE[j] = f2fma(cp, a1re, f2mul(sp, a0re));
                IM[j] = f2fma(cp, a1im, f2mul(sp, a0im));
            }
        }
    } else {
        // p == 0: half-swap butterfly
        const float2 cp = pk(c), ss = make_float2(-s, s);
#pragma unroll
        for (int k = 0; k < 16; ++k) {
            RE[k] = f2fma(cp, RE[k], f2mul(ss, swp(RE[k])));
            IM[k] = f2fma(cp, IM[k], f2mul(ss, swp(IM[k])));
        }
    }
}

// Gamma (composed diagonal): per-register phase multiply, coalesced loads
__device__ __forceinline__ void applyPhase(float2 RE[16], float2 IM[16], int lane, int g) {
    const float4* __restrict__ A = g_phA + g * 512 + lane;
    const float2* __restrict__ Bv = g_phB + g * 512 + lane;
#pragma unroll
    for (int k = 0; k < 16; ++k) {
        float4 a = A[k << 5];
        float2 ci = Bv[k << 5];
        float2 cr = make_float2(a.x, a.y), nci = make_float2(a.z, a.w);
        float2 nre = f2fma(cr, RE[k], f2mul(nci, IM[k]));
        float2 nim = f2fma(cr, IM[k], f2mul(ci, RE[k]));
        RE[k] = nre; IM[k] = nim;
    }
}

// ---------------------------------------------------------------------------
// CNOT cases
// ---------------------------------------------------------------------------
template <int CW, int TW>
__device__ __forceinline__ void cnotGate(float2 RE[16], float2 IM[16], int lane) {
    constexpr int pc = 9 - CW, pt = 9 - TW;
    if constexpr (pc >= 1 && pc <= 4 && pt >= 1 && pt <= 4) {
        constexpr int cm = 1 << (pc - 1), tm = 1 << (pt - 1);
#pragma unroll
        for (int k = 0; k < 16; ++k) {
            if ((k & cm) && !(k & tm)) {
                float2 a = RE[k]; RE[k] = RE[k | tm]; RE[k | tm] = a;
                float2 b = IM[k]; IM[k] = IM[k | tm]; IM[k | tm] = b;
            }
        }
    } else if constexpr (pc >= 1 && pc <= 4 && pt >= 5) {
        constexpr int cm = 1 << (pc - 1), tlm = 1 << (pt - 5);
#pragma unroll
        for (int k = 0; k < 16; ++k) {
            if (k & cm) { RE[k] = shx2(RE[k], tlm); IM[k] = shx2(IM[k], tlm); }
        }
    } else if constexpr (pc >= 1 && pc <= 4 && pt == 0) {
        constexpr int cm = 1 << (pc - 1);
#pragma unroll
        for (int k = 0; k < 16; ++k) {
            if (k & cm) { RE[k] = swp(RE[k]); IM[k] = swp(IM[k]); }
        }
    } else if constexpr (pc >= 5 && pt >= 1 && pt <= 4) {
        constexpr int tm = 1 << (pt - 1);
        bool c1 = (lane >> (pc - 5)) & 1;
#pragma unroll
        for (int k = 0; k < 16; ++k) {
            if (!(k & tm)) {
                float2 a = RE[k], b = RE[k | tm];
                RE[k] = c1 ? b : a; RE[k | tm] = c1 ? a : b;
                float2 e = IM[k], f = IM[k | tm];
                IM[k] = c1 ? f : e; IM[k | tm] = c1 ? e : f;
            }
        }
    } else if constexpr (pc >= 5 && pt == 0) {
        bool c1 = (lane >> (pc - 5)) & 1;
#pragma unroll
        for (int k = 0; k < 16; ++k) {
            float2 a = RE[k], b = IM[k];
            RE[k] = c1 ? swp(a) : a;
            IM[k] = c1 ? swp(b) : b;
        }
    } else if constexpr (pc == 0 && pt >= 5) {
        constexpr int tlm = 1 << (pt - 5);
#pragma unroll
        for (int k = 0; k < 16; ++k) {
            RE[k].y = __shfl_xor_sync(FULL, RE[k].y, tlm);
            IM[k].y = __shfl_xor_sync(FULL, IM[k].y, tlm);
        }
    } else if constexpr (pc == 0 && pt >= 1 && pt <= 4) {
        constexpr int tm = 1 << (pt - 1);
#pragma unroll
        for (int k = 0; k < 16; ++k) {
            if (!(k & tm)) {
                float t = RE[k].y; RE[k].y = RE[k | tm].y; RE[k | tm].y = t;
                float u = IM[k].y; IM[k].y = IM[k | tm].y; IM[k | tm].y = u;
            }
        }
    } else {
        constexpr int tlm = 1 << (pt - 5);
        int src = ((lane >> (pc - 5)) & 1) ? (lane ^ tlm) : lane;
#pragma unroll
        for (int k = 0; k < 16; ++k) { RE[k] = shidx2(RE[k], src); IM[k] = shidx2(IM[k], src); }
    }
}

// ---------------------------------------------------------------------------
// Sequencers
// ---------------------------------------------------------------------------
template <int W>
__device__ __forceinline__ void fusedSeq(float2 RE[16], float2 IM[16], int lane,
                                         float myc, float mys) {
    float cw = __shfl_sync(FULL, myc, W);
    float sw = __shfl_sync(FULL, mys, W);
    float4 g0 = g_rot[W * 2 + 0];
    float4 g1 = g_rot[W * 2 + 1];
    float2 U00 = make_float2(g0.x, g0.y), U01 = make_float2(g0.z, g0.w);
    float2 U10 = make_float2(g1.x, g1.y), U11 = make_float2(g1.z, g1.w);
    float2 F00 = make_float2(fmaf(U00.x, cw, U01.x * sw), fmaf(U00.y, cw, U01.y * sw));
    float2 F01 = make_float2(fmaf(U01.x, cw, -U00.x * sw), fmaf(U01.y, cw, -U00.y * sw));
    float2 F10 = make_float2(fmaf(U10.x, cw, U11.x * sw), fmaf(U10.y, cw, U11.y * sw));
    float2 F11 = make_float2(fmaf(U11.x, cw, -U10.x * sw), fmaf(U11.y, cw, -U10.y * sw));
    applyMat<W>(RE, IM, lane, F00, F01, F10, F11);
    if constexpr (W < NW - 1) fusedSeq<W + 1>(RE, IM, lane, myc, mys);
}

template <int W>
__device__ __forceinline__ void rySeq(float2 RE[16], float2 IM[16], int lane,
                                      const float2* __restrict__ cs) {
    float2 p = cs[W];
    ryGate<W>(RE, IM, lane, p.x, p.y);
    if constexpr (W < NW - 1) rySeq<W + 1>(RE, IM, lane, cs);
}

template <int R, int W>
__device__ __forceinline__ void cnotRest(float2 RE[16], float2 IM[16], int lane) {
    cnotGate<W, (W + R) % NW>(RE, IM, lane);
    if constexpr (W < NW - 1) cnotRest<R, W + 1>(RE, IM, lane);
}

template <int R>
__device__ __forceinline__ void cnotLayer(float2 RE[16], float2 IM[16], int lane) {
    int src = lane;
#pragma unroll
    for (int w = 4 - R; w >= 0; --w) {
        int cb = 4 - w, tb = 4 - w - R;
        src ^= (((src >> cb) & 1) << tb);
    }
#pragma unroll
    for (int k = 0; k < 16; ++k) { RE[k] = shidx2(RE[k], src); IM[k] = shidx2(IM[k], src); }
    cnotRest<R, 5 - R>(RE, IM, lane);
}

// ---------------------------------------------------------------------------
// Main kernel
// ---------------------------------------------------------------------------
__global__ void __launch_bounds__(128, 4)
vqc_kernel(const float* __restrict__ X, const float* __restrict__ bias,
           float* __restrict__ out, int B) {
    int warp = (blockIdx.x * blockDim.x + threadIdx.x) >> 5;
    int lane = threadIdx.x & 31;
    if (warp >= B) return;

    float x = (lane < NW) ? X[warp * NW + lane] : 0.0f;
    float mys, myc;
    sincosf(x * 0.78539816339744831f, &mys, &myc);

    float2 RE[16], IM[16];
#pragma unroll
    for (int k = 0; k < 16; ++k) { RE[k] = make_float2(0.f, 0.f); IM[k] = make_float2(0.f, 0.f); }
    RE[0].x = (lane == 0) ? 1.0f : 0.0f;

    // Layer 1 (encoding fused, RZ(om) deferred) + ring 1
    fusedSeq<0>(RE, IM, lane, myc, mys);
    cnotLayer<1>(RE, IM, lane);

    // Layers 2-4: Gamma (composed diagonals) + real RY layer + ring
#pragma unroll 1
    for (int g = 0; g < 3; ++g) {
        applyPhase(RE, IM, lane, g);
        rySeq<0>(RE, IM, lane, g_rycs + g * NW);
        switch (g) {
            case 0: cnotLayer<2>(RE, IM, lane); break;
            case 1: cnotLayer<3>(RE, IM, lane); break;
            default: break;  // ring 4 deferred to measurement mask
        }
    }

    // Z on wire 9 through deferred ring 4: parity mask half ^ k_bit3 ^ lane_bit3
    float2 accA = make_float2(0.f, 0.f);
    float2 accB = make_float2(0.f, 0.f);
#pragma unroll
    for (int k = 0; k < 8; ++k)
        accA = f2fma(RE[k], RE[k], f2fma(IM[k], IM[k], accA));
#pragma unroll
    for (int k = 8; k < 16; ++k)
        accB = f2fma(RE[k], RE[k], f2fma(IM[k], IM[k], accB));
    float z = (accA.x - accA.y) - (accB.x - accB.y);
    if ((lane >> 3) & 1) z = -z;
#pragma unroll
    for (int o = 16; o; o >>= 1) z += __shfl_xor_sync(FULL, z, o);
    if (lane == 0) out[warp] = z + bias[0];
}

// ---------------------------------------------------------------------------
extern "C" void kernel_launch(void* const* d_in, const int* in_sizes, int n_in,
                              void* d_out, int out_size) {
    const float* X = (const float*)d_in[0];
    const float* w = (const float*)d_in[1];
    const float* bias = (const float*)d_in[2];
    float* out = (float*)d_out;

    int B = in_sizes[0] / NW;

    prep_kernel<<<1, 1024>>>(w);

    int blocks = (B + 3) / 4;  // 4 warps per 128-thread block
    vqc_kernel<<<blocks, 128>>>(X, bias, out, B);
}